// round 12
// baseline (speedup 1.0000x reference)
#include <cuda_runtime.h>

// y[o*48+p, n, m] = sum_i W0[p,i] * t4[o, (n-1)%56, m, i]
// t4[o, n', m, i] = sum_{j,k} xpad[o, j, n', m+k] * W1[j,k,i]  (pad 3 each side, width)
//
// 112 CTAs (one per (o, out-row n)), 448 threads = 14 warps.
// Warp w owns m in [4w, 4w+4). Stage 2: lanes (i, m-pair), warp-private t4 slice,
// __syncwarp, stage 3 for the warp's own 4 m's. ONE __syncthreads total.

#define NCH 12
#define WID 56
#define XS 64               // xs row stride; xpad[q] at xs[j*64+q]; zeros [0,3)+[59,62)
#define KS 7
#define NI 9
#define NP 48
#define T4W 40              // per-warp t4 region stride: [i][4] (36) padded to 40
#define THREADS 448

__global__ __launch_bounds__(THREADS, 1)
void fused_sepconv_kernel(const float* __restrict__ x,
                          const float* __restrict__ W0,
                          const float* __restrict__ W1,
                          float* __restrict__ out) {
    __shared__ alignas(16) float xs[NCH * XS];        // 768
    __shared__ alignas(16) float w1s[NCH * KS * NI];  // 756
    __shared__ alignas(16) float w0s[NP * NI];        // 432
    __shared__ alignas(16) float t4s[14 * T4W];       // 560: warp-private [i][4] slices

    const int b = blockIdx.x;             // 0..111
    const int o = b / WID;
    const int n = b % WID;
    const int nin = (n + WID - 1) % WID;  // roll(+1) along height
    const int t = threadIdx.x;
    const int w = t >> 5;                 // warp 0..13
    const int l = t & 31;

    // ---- Phase 1: all global loads issued first (max MLP), then scatter ----
    float4 xv = make_float4(0.f, 0.f, 0.f, 0.f);
    float4 w1v = make_float4(0.f, 0.f, 0.f, 0.f);
    float w0v = 0.f;
    if (t < 168) {
        int j  = t / 14;
        int q4 = t % 14;
        xv = *(const float4*)&x[(((o * NCH + j) * WID + nin) * WID) + 4 * q4];
    } else if (t < 357) {
        w1v = *(const float4*)&W1[4 * (t - 168)];
    }
    if (t < 432) w0v = W0[t];

    if (t < 168) {
        int j  = t / 14;
        int q4 = t % 14;
        float* dst = &xs[j * XS + 3 + 4 * q4];    // x col c -> xs idx c+3 (== xpad idx)
        dst[0] = xv.x; dst[1] = xv.y; dst[2] = xv.z; dst[3] = xv.w;
        if (q4 == 0) {
            xs[j * XS + 0] = 0.f; xs[j * XS + 1] = 0.f; xs[j * XS + 2] = 0.f;
        } else if (q4 == 13) {
            xs[j * XS + 59] = 0.f; xs[j * XS + 60] = 0.f; xs[j * XS + 61] = 0.f;
        }
    } else if (t < 357) {
        *(float4*)&w1s[4 * (t - 168)] = w1v;
    }
    if (t < 432) w0s[t] = w0v;

    __syncthreads();   // the ONLY block barrier

    // ---- Stage 2 (warp-local): lanes 0..17 = (half h, i); 2 m's per lane ----
    if (l < 18) {
        const int h  = l / NI;            // 0,1
        const int i  = l % NI;            // i lane-fast: w1 reads consecutive
        const int m0 = 4 * w + 2 * h;     // even -> aligned float2 window reads

        float a0 = 0.f, a1 = 0.f;         // output m0  (2 chains)
        float b0 = 0.f, b1 = 0.f;         // output m0+1

        #pragma unroll
        for (int j = 0; j < NCH; ++j) {
            // window xpad[m0 .. m0+7] = 4 aligned float2
            const float2* xg = (const float2*)&xs[j * XS + m0];
            float2 g0 = xg[0], g1 = xg[1], g2 = xg[2], g3 = xg[3];
            const float xw[8] = {g0.x, g0.y, g1.x, g1.y, g2.x, g2.y, g3.x, g3.y};
            const float* wj = &w1s[(j * KS) * NI + i];

            #pragma unroll
            for (int k = 0; k < KS; ++k) {
                const float wv = wj[k * NI];
                if (k & 1) {
                    a1 = fmaf(xw[k],     wv, a1);
                    b1 = fmaf(xw[k + 1], wv, b1);
                } else {
                    a0 = fmaf(xw[k],     wv, a0);
                    b0 = fmaf(xw[k + 1], wv, b0);
                }
            }
        }
        // warp-private [i][4]; pair at offset 2h -> 8B-aligned float2 store
        *(float2*)&t4s[w * T4W + i * 4 + 2 * h] = make_float2(a0 + a1, b0 + b1);
    }

    __syncwarp();      // warp-local producer->consumer hand-off

    // ---- Stage 3 (warp-local): warp's quad m0 = 4w; 48 p-outputs, <=2 per lane ----
    const int m0 = 4 * w;
    #pragma unroll
    for (int r = 0; r < 2; ++r) {
        const int p = r * 32 + l;
        if (p < NP) {
            const float* w0row = &w0s[p * NI];   // stride-9 scalar reads
            float4 res = make_float4(0.f, 0.f, 0.f, 0.f);
            float* rp = (float*)&res;
            #pragma unroll
            for (int i = 0; i < NI; ++i) {
                float4 tq = *(const float4*)&t4s[w * T4W + i * 4];  // broadcast LDS.128
                const float wv = w0row[i];
                rp[0] = fmaf(tq.x, wv, rp[0]);
                rp[1] = fmaf(tq.y, wv, rp[1]);
                rp[2] = fmaf(tq.z, wv, rp[2]);
                rp[3] = fmaf(tq.w, wv, rp[3]);
            }
            *(float4*)&out[(((o * NP + p) * WID + n) * WID) + m0] = res;
        }
    }
}

extern "C" void kernel_launch(void* const* d_in, const int* in_sizes, int n_in,
                              void* d_out, int out_size) {
    // Bind inputs by size: x=75264, W0=432, W1=756
    const float* x  = (const float*)d_in[0];
    const float* W0 = (const float*)d_in[1];
    const float* W1 = (const float*)d_in[2];
    for (int i = 0; i < n_in; ++i) {
        if (in_sizes[i] == 75264) x  = (const float*)d_in[i];
        else if (in_sizes[i] == 432) W0 = (const float*)d_in[i];
        else if (in_sizes[i] == 756) W1 = (const float*)d_in[i];
    }
    float* out = (float*)d_out;

    fused_sepconv_kernel<<<2 * WID, THREADS>>>(x, W0, W1, out);
}

// round 13
// speedup vs baseline: 1.0037x; 1.0037x over previous
#include <cuda_runtime.h>

// y[o*48+p, n, m] = sum_i W0[p,i] * t4[o, (n-1)%56, m, i]
// t4[o, n', m, i] = sum_{j,k} xpad[o, j, n', m+k] * W1[j,k,i]  (pad 3 each side, width)
//
// ZERO block barriers. 112 CTAs, 224 threads = 7 fully autonomous warps.
// Warp w owns m in [8w, 8w+8): loads its own x window into warp-private smem,
// __syncwarp, stage 2 (weights via LDG, L1-cached), __syncwarp, stage 3.

#define NCH 12
#define WID 56
#define XWS 16              // warp-private x row stride (floats); 12 rows per warp
#define KS 7
#define NI 9
#define NP 48
#define T4W 80              // per-warp t4 region: [i][8] padded
#define THREADS 224

__global__ __launch_bounds__(THREADS, 1)
void fused_sepconv_kernel(const float* __restrict__ x,
                          const float* __restrict__ W0,
                          const float* __restrict__ W1,
                          float* __restrict__ out) {
    // per-warp x window: xw[w][j][c] = xpad[o, j, nin, 8w + c], c in [0,14)
    __shared__ alignas(16) float xw[7 * NCH * XWS];   // 1344
    __shared__ alignas(16) float t4s[7 * T4W];        // 560: warp-private [i][8]

    const int b = blockIdx.x;             // 0..111
    const int o = b / WID;
    const int n = b % WID;
    const int nin = (n + WID - 1) % WID;  // roll(+1) along height
    const int t = threadIdx.x;
    const int w = t >> 5;                 // warp 0..6
    const int l = t & 31;

    const int xrow = ((o * NCH) * WID + nin) * WID;   // base of channel 0's row
    float* xwp = &xw[w * NCH * XWS];

    // ---- Phase 1 (warp-local): 168 predicated scalar loads, 6 rounds ----
    // xpad col = x col + 3; xw[j][c] holds xpad[8w + c] = x[8w + c - 3]
    float v[6];
    #pragma unroll
    for (int r = 0; r < 6; ++r) {
        const int idx = r * 32 + l;
        v[r] = 0.f;
        if (idx < NCH * 14) {
            const int j   = idx / 14;
            const int c   = idx % 14;
            const int col = 8 * w + c - 3;
            if (col >= 0 && col < WID)
                v[r] = x[xrow + j * WID * WID + col];
        }
    }
    #pragma unroll
    for (int r = 0; r < 6; ++r) {
        const int idx = r * 32 + l;
        if (idx < NCH * 14) {
            const int j = idx / 14;
            const int c = idx % 14;
            xwp[j * XWS + c] = v[r];
        }
    }

    __syncwarp();

    // ---- Stage 2 (warp-local): lanes 0..17 = (quad q, i); weights via LDG ----
    if (l < 18) {
        const int q = l / NI;             // 0,1
        const int i = l % NI;             // i lane-fast -> coalesced W1 LDG
        const int c0 = 4 * q;             // local window base (aligned)

        float a0 = 0.f, a1 = 0.f, a2 = 0.f, a3 = 0.f;  // outputs 8w+4q+{0..3}

        #pragma unroll
        for (int j = 0; j < NCH; ++j) {
            // window xpad[8w+4q .. +9] = xw cols c0..c0+9 = 5 aligned float2
            const float2* xg = (const float2*)&xwp[j * XWS + c0];
            float2 g0 = xg[0], g1 = xg[1], g2 = xg[2], g3 = xg[3], g4 = xg[4];
            const float xv[10] = {g0.x, g0.y, g1.x, g1.y, g2.x,
                                  g2.y, g3.x, g3.y, g4.x, g4.y};
            const float* wj = &W1[(j * KS) * NI + i];

            #pragma unroll
            for (int k = 0; k < KS; ++k) {
                const float wv = wj[k * NI];      // LDG, L1/L2-cached, coalesced
                a0 = fmaf(xv[k],     wv, a0);
                a1 = fmaf(xv[k + 1], wv, a1);
                a2 = fmaf(xv[k + 2], wv, a2);
                a3 = fmaf(xv[k + 3], wv, a3);
            }
        }
        *(float4*)&t4s[w * T4W + i * 8 + 4 * q] = make_float4(a0, a1, a2, a3);
    }

    __syncwarp();

    // ---- Stage 3 (warp-local): 96 float4 outputs per warp, 3 per lane ----
    #pragma unroll
    for (int r = 0; r < 3; ++r) {
        const int idx = r * 32 + l;       // 0..95
        const int p   = idx % NP;
        const int mq  = idx / NP;         // 0,1
        const int m0  = 8 * w + 4 * mq;

        const float* w0row = &W0[p * NI];    // LDG, L1/L2-cached
        float4 res = make_float4(0.f, 0.f, 0.f, 0.f);
        float* rp = (float*)&res;
        #pragma unroll
        for (int i = 0; i < NI; ++i) {
            float4 tq = *(const float4*)&t4s[w * T4W + i * 8 + 4 * mq];  // broadcast
            const float wv = w0row[i];
            rp[0] = fmaf(tq.x, wv, rp[0]);
            rp[1] = fmaf(tq.y, wv, rp[1]);
            rp[2] = fmaf(tq.z, wv, rp[2]);
            rp[3] = fmaf(tq.w, wv, rp[3]);
        }
        *(float4*)&out[(((o * NP + p) * WID + n) * WID) + m0] = res;
    }
}

extern "C" void kernel_launch(void* const* d_in, const int* in_sizes, int n_in,
                              void* d_out, int out_size) {
    // Bind inputs by size: x=75264, W0=432, W1=756
    const float* x  = (const float*)d_in[0];
    const float* W0 = (const float*)d_in[1];
    const float* W1 = (const float*)d_in[2];
    for (int i = 0; i < n_in; ++i) {
        if (in_sizes[i] == 75264) x  = (const float*)d_in[i];
        else if (in_sizes[i] == 432) W0 = (const float*)d_in[i];
        else if (in_sizes[i] == 756) W1 = (const float*)d_in[i];
    }
    float* out = (float*)d_out;

    fused_sepconv_kernel<<<2 * WID, THREADS>>>(x, W0, W1, out);
}

// round 14
// speedup vs baseline: 1.3204x; 1.3155x over previous
#include <cuda_runtime.h>

// y[o*48+p, n, m] = sum_i W0[p,i] * t4[o, (n-1)%56, m, i]
// t4[o, n', m, i] = sum_{j,k} xpad[o, j, n', m+k] * W1[j,k,i]  (pad 3 each side, width)
//
// 112 CTAs (one per (o, out-row n)), 224 threads = 7 warps, ONE block barrier.
// Warp w owns m in [8w, 8w+8). Stage-3 W0 operands prefetched into registers
// right after the barrier (independent of t4) so they overlap stage-2 compute.

#define NCH 12
#define WID 56
#define XS 64               // xs row stride; xpad[q] at xs[j*64+q]; zeros [0,3)+[59,62)
#define KS 7
#define NI 9
#define NP 48
#define T4W 80              // per-warp t4 region stride: [i][8] padded
#define THREADS 224

__global__ __launch_bounds__(THREADS, 1)
void fused_sepconv_kernel(const float* __restrict__ x,
                          const float* __restrict__ W0,
                          const float* __restrict__ W1,
                          float* __restrict__ out) {
    __shared__ alignas(16) float xs[NCH * XS];        // 768
    __shared__ alignas(16) float w1s[NCH * KS * NI];  // 756
    __shared__ alignas(16) float w0s[NP * NI];        // 432
    __shared__ alignas(16) float t4s[7 * T4W];        // 560: warp-private [i][8] slices

    const int b = blockIdx.x;             // 0..111
    const int o = b / WID;
    const int n = b % WID;
    const int nin = (n + WID - 1) % WID;  // roll(+1) along height
    const int t = threadIdx.x;
    const int w = t >> 5;                 // warp 0..6
    const int l = t & 31;

    // ---- Phase 1: all global loads issued first (max MLP), then scatter ----
    float4 xv = make_float4(0.f, 0.f, 0.f, 0.f);
    float4 w1v = make_float4(0.f, 0.f, 0.f, 0.f);
    float w0a = 0.f, w0b = 0.f;
    if (t < 168) {
        int j  = t / 14;
        int q4 = t % 14;
        xv = *(const float4*)&x[(((o * NCH + j) * WID + nin) * WID) + 4 * q4];
    }
    if (t < 189) w1v = *(const float4*)&W1[4 * t];
    if (t < 216) { w0a = W0[t]; w0b = W0[t + 216]; }

    if (t < 168) {
        int j  = t / 14;
        int q4 = t % 14;
        float* dst = &xs[j * XS + 3 + 4 * q4];   // x col c -> xs idx c+3 (== xpad idx)
        dst[0] = xv.x; dst[1] = xv.y; dst[2] = xv.z; dst[3] = xv.w;
        if (q4 == 0) {
            xs[j * XS + 0] = 0.f; xs[j * XS + 1] = 0.f; xs[j * XS + 2] = 0.f;
        } else if (q4 == 13) {
            xs[j * XS + 59] = 0.f; xs[j * XS + 60] = 0.f; xs[j * XS + 61] = 0.f;
        }
    }
    if (t < 189) *(float4*)&w1s[4 * t] = w1v;
    if (t < 216) { w0s[t] = w0a; w0s[t + 216] = w0b; }

    __syncthreads();   // the ONLY block barrier

    // ---- Prefetch stage-3 W0 rows into registers (independent of t4) ----
    // lane handles items idx = r*32 + l, r in [0,3): p = idx%48, mq = idx/48.
    float w0r[3][NI];
    #pragma unroll
    for (int r = 0; r < 3; ++r) {
        const int p = (r * 32 + l) % NP;
        #pragma unroll
        for (int i = 0; i < NI; ++i)
            w0r[r][i] = w0s[p * NI + i];   // stride-9 reads, conflict-free
    }

    // ---- Stage 2 (warp-local): lanes 0..17 = (quad q, i); 4-m quad per lane ----
    if (l < 18) {
        const int q  = l / NI;            // 0,1
        const int i  = l % NI;            // lanes i-fast: w1 reads consecutive
        const int m0 = 8 * w + 4 * q;     // global m base of this quad

        float a0 = 0.f, a1 = 0.f, a2 = 0.f, a3 = 0.f;  // outputs m0..m0+3

        #pragma unroll
        for (int j = 0; j < NCH; ++j) {
            // window xpad[m0 .. m0+9] = 5 aligned float2
            const float2* xg = (const float2*)&xs[j * XS + m0];
            float2 g0 = xg[0], g1 = xg[1], g2 = xg[2], g3 = xg[3], g4 = xg[4];
            const float xw[10] = {g0.x, g0.y, g1.x, g1.y, g2.x,
                                  g2.y, g3.x, g3.y, g4.x, g4.y};
            const float* wj = &w1s[(j * KS) * NI + i];

            #pragma unroll
            for (int k = 0; k < KS; ++k) {
                const float wv = wj[k * NI];
                a0 = fmaf(xw[k],     wv, a0);
                a1 = fmaf(xw[k + 1], wv, a1);
                a2 = fmaf(xw[k + 2], wv, a2);
                a3 = fmaf(xw[k + 3], wv, a3);
            }
        }
        // warp-private region: [i][8], quad at offset 4q -> 16B-aligned float4 store
        *(float4*)&t4s[w * T4W + i * 8 + 4 * q] = make_float4(a0, a1, a2, a3);
    }

    __syncwarp();      // warp-local producer->consumer hand-off

    // ---- Stage 3 (warp-local): 96 float4 outputs per warp, 3 per lane ----
    #pragma unroll
    for (int r = 0; r < 3; ++r) {
        const int idx = r * 32 + l;       // 0..95
        const int p   = idx % NP;
        const int mq  = idx / NP;         // 0,1
        const int m0  = 8 * w + 4 * mq;

        float4 res = make_float4(0.f, 0.f, 0.f, 0.f);
        float* rp = (float*)&res;
        #pragma unroll
        for (int i = 0; i < NI; ++i) {
            float4 tq = *(const float4*)&t4s[w * T4W + i * 8 + 4 * mq];  // broadcast
            const float wv = w0r[r][i];   // register, no LDS
            rp[0] = fmaf(tq.x, wv, rp[0]);
            rp[1] = fmaf(tq.y, wv, rp[1]);
            rp[2] = fmaf(tq.z, wv, rp[2]);
            rp[3] = fmaf(tq.w, wv, rp[3]);
        }
        *(float4*)&out[(((o * NP + p) * WID + n) * WID) + m0] = res;
    }
}

extern "C" void kernel_launch(void* const* d_in, const int* in_sizes, int n_in,
                              void* d_out, int out_size) {
    // Bind inputs by size: x=75264, W0=432, W1=756
    const float* x  = (const float*)d_in[0];
    const float* W0 = (const float*)d_in[1];
    const float* W1 = (const float*)d_in[2];
    for (int i = 0; i < n_in; ++i) {
        if (in_sizes[i] == 75264) x  = (const float*)d_in[i];
        else if (in_sizes[i] == 432) W0 = (const float*)d_in[i];
        else if (in_sizes[i] == 756) W1 = (const float*)d_in[i];
    }
    float* out = (float*)d_out;

    fused_sepconv_kernel<<<2 * WID, THREADS>>>(x, W0, W1, out);
}